// round 11
// baseline (speedup 1.0000x reference)
#include <cuda_runtime.h>
#include <cuda_fp16.h>

// PassiveWaveDigitalMixer — fused 9-point periodic stencil + gated flows.
// B=4, C=128, H=W=256, O=16, M=32 (fixed shapes).
// R10: R5 4-row structure + full 12-load front-batch, but steer multipliers
// live in SHARED (3x LDS.128 per row) so the body fits ~80 regs, and the
// channel range is split across gridDim.z=2 so grid=512 supports 3 CTAs/SM
// -> 24 warps x 12 batched LDG.128 = ~36KB in flight per SM.

constexpr int B = 4, C = 128, H = 256, W = 256, O = 16, M = 32;
constexpr int HW = H * W;
constexpr float GAIN_CAP = 0.99f;
constexpr float EPS = 1e-4f;

__device__ __forceinline__ float softplus_eps(float p) {
    return fmaxf(p, 0.0f) + log1pf(expf(-fabsf(p))) + EPS;
}

__device__ __forceinline__ float4 add4(float4 a, float4 b) {
    return make_float4(a.x + b.x, a.y + b.y, a.z + b.z, a.w + b.w);
}

__device__ __forceinline__ __half2 u2h(unsigned u) {
    __half2 r;
    *reinterpret_cast<unsigned*>(&r) = u;
    return r;
}

__global__ __launch_bounds__(256, 3)
void pwdm_kernel(const float* __restrict__ x,
                 const float* __restrict__ steer,
                 const float* __restrict__ modulation,
                 const float* __restrict__ r_center,
                 const float* __restrict__ r_horizontal,
                 const float* __restrict__ r_vertical,
                 const float* __restrict__ r_diag,
                 const float* __restrict__ gain_h,
                 const float* __restrict__ gain_v,
                 const float* __restrict__ gain_d,
                 const float* __restrict__ steer_w,
                 const float* __restrict__ mod_w,
                 float* __restrict__ out)
{
    __shared__ float s_invh[C], s_invv[C], s_invd[C];
    __shared__ float s_gh[C],   s_gv[C],   s_gd[C];
    __shared__ __half s_t[4][3][W];   // pre-expanded (1 + 0.2*tanh(field))

    const int tx  = threadIdx.x;          // 0..31 lane (8 w-elems each)
    const int ty  = threadIdx.y;          // 0..7  channel sub-lane
    const int tid = ty * 32 + tx;
    const int h0  = blockIdx.x * 4;       // first of the 4-row group
    const int b   = blockIdx.y;
    const int cbase = blockIdx.z * (C / 2);  // channel half [0,64) or [64,128)

    // --- modulation deltas (broadcast loads, every thread) ---
    float d0 = 0.f, d1 = 0.f, d2 = 0.f;
    #pragma unroll
    for (int m = 0; m < M; m++) {
        float mv = modulation[b * M + m];
        d0 = fmaf(mv, mod_w[0 * M + m], d0);
        d1 = fmaf(mv, mod_w[1 * M + m], d1);
        d2 = fmaf(mv, mod_w[2 * M + m], d2);
    }
    d0 = tanhf(d0); d1 = tanhf(d1); d2 = tanhf(d2);

    // --- per-channel constants (all 128; cheap, keeps indexing simple) ---
    if (tid < C) {
        float spc = softplus_eps(r_center[tid]);
        s_invh[tid] = 1.0f / (spc + softplus_eps(r_horizontal[tid]));
        s_invv[tid] = 1.0f / (spc + softplus_eps(r_vertical[tid]));
        s_invd[tid] = 1.0f / (2.0f * (spc + softplus_eps(r_diag[tid])));
        s_gh[tid] = tanhf(gain_h[tid]) * (1.0f + 0.1f * d0);
        s_gv[tid] = tanhf(gain_v[tid]) * (1.0f + 0.1f * d1);
        s_gd[tid] = tanhf(gain_d[tid]) * (1.0f + 0.1f * d2);
    }

    // --- steer-field multipliers, vectorized: thread covers one row (tid>>6)
    //     and 4 consecutive w positions ((tid&63)*4) via float4 loads ---
    {
        const int r  = tid >> 6;          // 0..3
        const int wq = (tid & 63) * 4;    // w base
        float4 a0 = make_float4(0.f, 0.f, 0.f, 0.f);
        float4 a1 = a0, a2 = a0;
        const float4* sp = reinterpret_cast<const float4*>(
            steer + ((size_t)b * O * H + (h0 + r)) * W + wq);
        const int planeF4 = HW / 4;
        #pragma unroll
        for (int o = 0; o < O; o++) {
            float4 sv = sp[(size_t)o * planeF4];
            float w0c = steer_w[0 * O + o];
            float w1c = steer_w[1 * O + o];
            float w2c = steer_w[2 * O + o];
            a0.x = fmaf(sv.x, w0c, a0.x); a0.y = fmaf(sv.y, w0c, a0.y);
            a0.z = fmaf(sv.z, w0c, a0.z); a0.w = fmaf(sv.w, w0c, a0.w);
            a1.x = fmaf(sv.x, w1c, a1.x); a1.y = fmaf(sv.y, w1c, a1.y);
            a1.z = fmaf(sv.z, w1c, a1.z); a1.w = fmaf(sv.w, w1c, a1.w);
            a2.x = fmaf(sv.x, w2c, a2.x); a2.y = fmaf(sv.y, w2c, a2.y);
            a2.z = fmaf(sv.z, w2c, a2.z); a2.w = fmaf(sv.w, w2c, a2.w);
        }
        // pack (1 + 0.2*tanh) into half2 pairs, 2 STS.32 per dir
        #pragma unroll
        for (int d = 0; d < 3; d++) {
            float4 a = (d == 0) ? a0 : (d == 1) ? a1 : a2;
            __half2 lo = __floats2half2_rn(fmaf(0.2f, tanhf(a.x), 1.0f),
                                           fmaf(0.2f, tanhf(a.y), 1.0f));
            __half2 hi = __floats2half2_rn(fmaf(0.2f, tanhf(a.z), 1.0f),
                                           fmaf(0.2f, tanhf(a.w), 1.0f));
            *reinterpret_cast<__half2*>(&s_t[r][d][wq])     = lo;
            *reinterpret_cast<__half2*>(&s_t[r][d][wq + 2]) = hi;
        }
    }
    __syncthreads();

    const int w0 = tx * 8;
    const int hm = (h0 - 1) & (H - 1);
    const int hp = (h0 + 4) & (H - 1);
    const size_t base = (size_t)b * C * HW + (size_t)(cbase + ty) * HW + w0;
    const float* pm = x + base + (size_t)hm * W;
    const float* p0 = x + base + (size_t)h0 * W;
    const float* pp = x + base + (size_t)hp * W;
    float*       o0 = out + base + (size_t)h0 * W;
    const size_t cstep = (size_t)8 * HW;

    const unsigned FULL = 0xffffffffu;
    const int laneL = (tx + 31) & 31;
    const int laneR = (tx + 1) & 31;
    const __half2 zero2 = __float2half2_rn(0.0f);
    const __half2 cap2  = __float2half2_rn(GAIN_CAP);

    float invh, invv, invd;
    __half2 gh2, gv2, gd2;

    // one output row: centers (cA,cB), vertical sums (sA,sB); steer mults
    // read from shared via 3x LDS.128 (channel-invariant, re-read per row).
    auto do_row = [&](float4 cA_, float4 cB_, float4 sA_, float4 sB_,
                      int r, float* op) {
        uint4 uH = *reinterpret_cast<const uint4*>(&s_t[r][0][w0]);
        uint4 uV = *reinterpret_cast<const uint4*>(&s_t[r][1][w0]);
        uint4 uD = *reinterpret_cast<const uint4*>(&s_t[r][2][w0]);
        unsigned mh[4] = {uH.x, uH.y, uH.z, uH.w};
        unsigned mv[4] = {uV.x, uV.y, uV.z, uV.w};
        unsigned md[4] = {uD.x, uD.y, uD.z, uD.w};

        float ce[10], se[10];
        ce[1] = cA_.x; ce[2] = cA_.y; ce[3] = cA_.z; ce[4] = cA_.w;
        ce[5] = cB_.x; ce[6] = cB_.y; ce[7] = cB_.z; ce[8] = cB_.w;
        se[1] = sA_.x; se[2] = sA_.y; se[3] = sA_.z; se[4] = sA_.w;
        se[5] = sB_.x; se[6] = sB_.y; se[7] = sB_.z; se[8] = sB_.w;
        ce[0] = __shfl_sync(FULL, ce[8], laneL);
        ce[9] = __shfl_sync(FULL, ce[1], laneR);
        se[0] = __shfl_sync(FULL, se[8], laneL);
        se[9] = __shfl_sync(FULL, se[1], laneR);

        float r8[8];
        #pragma unroll
        for (int j = 0; j < 4; j++) {
            __half2 gH = __hmin2(__hmax2(__hmul2(gh2, u2h(mh[j])), zero2), cap2);
            __half2 gV = __hmin2(__hmax2(__hmul2(gv2, u2h(mv[j])), zero2), cap2);
            __half2 gD = __hmin2(__hmax2(__hmul2(gd2, u2h(md[j])), zero2), cap2);
            float2 ghf = __half22float2(gH);
            float2 gvf = __half22float2(gV);
            float2 gdf = __half22float2(gD);
            #pragma unroll
            for (int k = 0; k < 2; k++) {
                const int i = 2 * j + k;
                float cv = ce[i + 1];
                float fh = (ce[i] + ce[i + 2] - 2.0f * cv) * invh;
                float fv = (se[i + 1]          - 2.0f * cv) * invv;
                float fd = (se[i] + se[i + 2]  - 4.0f * cv) * invd;
                float gh = k ? ghf.y : ghf.x;
                float gv = k ? gvf.y : gvf.x;
                float gd = k ? gdf.y : gdf.x;
                r8[i] = fmaf(gh, fh, fmaf(gv, fv, fmaf(gd, fd, cv)));
            }
        }
        __stcs(reinterpret_cast<float4*>(op),
               make_float4(r8[0], r8[1], r8[2], r8[3]));
        __stcs(reinterpret_cast<float4*>(op + 4),
               make_float4(r8[4], r8[5], r8[6], r8[7]));
    };

    for (int c = cbase + ty; c < cbase + C / 2; c += 8) {
        // front-batch ALL 12 row-vector loads (rows m, a, b, c, d, p)
        float4 mA = *reinterpret_cast<const float4*>(pm);
        float4 mB = *reinterpret_cast<const float4*>(pm + 4);
        float4 aA = *reinterpret_cast<const float4*>(p0);
        float4 aB = *reinterpret_cast<const float4*>(p0 + 4);
        float4 bA = *reinterpret_cast<const float4*>(p0 + W);
        float4 bB = *reinterpret_cast<const float4*>(p0 + W + 4);
        float4 cA = *reinterpret_cast<const float4*>(p0 + 2 * W);
        float4 cB = *reinterpret_cast<const float4*>(p0 + 2 * W + 4);
        float4 dA = *reinterpret_cast<const float4*>(p0 + 3 * W);
        float4 dB = *reinterpret_cast<const float4*>(p0 + 3 * W + 4);
        float4 pA = *reinterpret_cast<const float4*>(pp);
        float4 pB = *reinterpret_cast<const float4*>(pp + 4);

        invh = s_invh[c]; invv = s_invv[c]; invd = s_invd[c];
        gh2 = __float2half2_rn(s_gh[c]);
        gv2 = __float2half2_rn(s_gv[c]);
        gd2 = __float2half2_rn(s_gd[c]);

        // row h0: vsum = m + b  (m dies)
        do_row(aA, aB, add4(mA, bA), add4(mB, bB), 0, o0);
        // row h1: vsum = a + c  (a dies)
        do_row(bA, bB, add4(aA, cA), add4(aB, cB), 1, o0 + W);
        // row h2: vsum = b + d  (b dies)
        do_row(cA, cB, add4(bA, dA), add4(bB, dB), 2, o0 + 2 * W);
        // row h3: vsum = c + p
        do_row(dA, dB, add4(cA, pA), add4(cB, pB), 3, o0 + 3 * W);

        pm += cstep; p0 += cstep; pp += cstep; o0 += cstep;
    }
}

extern "C" void kernel_launch(void* const* d_in, const int* in_sizes, int n_in,
                              void* d_out, int out_size)
{
    const float* x            = (const float*)d_in[0];
    const float* steer        = (const float*)d_in[1];
    const float* modulation   = (const float*)d_in[2];
    const float* r_center     = (const float*)d_in[3];
    const float* r_horizontal = (const float*)d_in[4];
    const float* r_vertical   = (const float*)d_in[5];
    const float* r_diag       = (const float*)d_in[6];
    const float* gain_h       = (const float*)d_in[7];
    const float* gain_v       = (const float*)d_in[8];
    const float* gain_d       = (const float*)d_in[9];
    const float* steer_w      = (const float*)d_in[10];
    const float* mod_w        = (const float*)d_in[11];
    float* out = (float*)d_out;

    dim3 block(32, 8, 1);       // one warp per full W row-quad, 8 channel lanes
    dim3 grid(H / 4, B, 2);     // 4-row groups x batch x 2 channel halves = 512
    pwdm_kernel<<<grid, block>>>(x, steer, modulation,
                                 r_center, r_horizontal, r_vertical, r_diag,
                                 gain_h, gain_v, gain_d,
                                 steer_w, mod_w, out);
}

// round 12
// speedup vs baseline: 1.2722x; 1.2722x over previous
#include <cuda_runtime.h>
#include <cuda_fp16.h>

// PassiveWaveDigitalMixer — fused 9-point periodic stencil + gated flows.
// B=4, C=128, H=W=256, O=16, M=32 (fixed shapes).
// R11 = R5 (best: warp = full W row x 4 consecutive h rows per channel
// iteration, 12 front-batched LDG.128, steer multipliers as half2 in
// REGISTERS, packed-half2 gating, fp32 flows, 128 regs / 2 CTA/SM)
//   + vectorized steer prologue (float4 loads, thread = 1 row x 4 w)
//   + __stcs output stores (evict-first; keep L2 for x halo reuse).

constexpr int B = 4, C = 128, H = 256, W = 256, O = 16, M = 32;
constexpr int HW = H * W;
constexpr float GAIN_CAP = 0.99f;
constexpr float EPS = 1e-4f;

__device__ __forceinline__ float softplus_eps(float p) {
    return fmaxf(p, 0.0f) + log1pf(expf(-fabsf(p))) + EPS;
}

__device__ __forceinline__ float4 add4(float4 a, float4 b) {
    return make_float4(a.x + b.x, a.y + b.y, a.z + b.z, a.w + b.w);
}

__global__ __launch_bounds__(256, 2)
void pwdm_kernel(const float* __restrict__ x,
                 const float* __restrict__ steer,
                 const float* __restrict__ modulation,
                 const float* __restrict__ r_center,
                 const float* __restrict__ r_horizontal,
                 const float* __restrict__ r_vertical,
                 const float* __restrict__ r_diag,
                 const float* __restrict__ gain_h,
                 const float* __restrict__ gain_v,
                 const float* __restrict__ gain_d,
                 const float* __restrict__ steer_w,
                 const float* __restrict__ mod_w,
                 float* __restrict__ out)
{
    __shared__ float s_invh[C], s_invv[C], s_invd[C];
    __shared__ float s_gh[C],   s_gv[C],   s_gd[C];
    __shared__ __half s_t[4][3][W];   // pre-expanded (1 + 0.2*tanh(field))

    const int tx  = threadIdx.x;          // 0..31 lane (8 w-elems each)
    const int ty  = threadIdx.y;          // 0..7  channel sub-lane
    const int tid = ty * 32 + tx;
    const int h0  = blockIdx.x * 4;       // first of the 4-row group
    const int b   = blockIdx.y;

    // --- modulation deltas (broadcast loads, every thread) ---
    float d0 = 0.f, d1 = 0.f, d2 = 0.f;
    #pragma unroll
    for (int m = 0; m < M; m++) {
        float mv = modulation[b * M + m];
        d0 = fmaf(mv, mod_w[0 * M + m], d0);
        d1 = fmaf(mv, mod_w[1 * M + m], d1);
        d2 = fmaf(mv, mod_w[2 * M + m], d2);
    }
    d0 = tanhf(d0); d1 = tanhf(d1); d2 = tanhf(d2);

    // --- per-channel constants ---
    if (tid < C) {
        float spc = softplus_eps(r_center[tid]);
        s_invh[tid] = 1.0f / (spc + softplus_eps(r_horizontal[tid]));
        s_invv[tid] = 1.0f / (spc + softplus_eps(r_vertical[tid]));
        s_invd[tid] = 1.0f / (2.0f * (spc + softplus_eps(r_diag[tid])));
        s_gh[tid] = tanhf(gain_h[tid]) * (1.0f + 0.1f * d0);
        s_gv[tid] = tanhf(gain_v[tid]) * (1.0f + 0.1f * d1);
        s_gd[tid] = tanhf(gain_d[tid]) * (1.0f + 0.1f * d2);
    }

    // --- steer-field multipliers, vectorized: thread covers row (tid>>6)
    //     and 4 consecutive w positions via float4 loads ---
    {
        const int r  = tid >> 6;          // 0..3
        const int wq = (tid & 63) * 4;    // w base
        float4 a0 = make_float4(0.f, 0.f, 0.f, 0.f);
        float4 a1 = a0, a2 = a0;
        const float4* sp = reinterpret_cast<const float4*>(
            steer + ((size_t)b * O * H + (h0 + r)) * W + wq);
        const int planeF4 = HW / 4;
        #pragma unroll
        for (int o = 0; o < O; o++) {
            float4 sv = sp[(size_t)o * planeF4];
            float w0c = steer_w[0 * O + o];
            float w1c = steer_w[1 * O + o];
            float w2c = steer_w[2 * O + o];
            a0.x = fmaf(sv.x, w0c, a0.x); a0.y = fmaf(sv.y, w0c, a0.y);
            a0.z = fmaf(sv.z, w0c, a0.z); a0.w = fmaf(sv.w, w0c, a0.w);
            a1.x = fmaf(sv.x, w1c, a1.x); a1.y = fmaf(sv.y, w1c, a1.y);
            a1.z = fmaf(sv.z, w1c, a1.z); a1.w = fmaf(sv.w, w1c, a1.w);
            a2.x = fmaf(sv.x, w2c, a2.x); a2.y = fmaf(sv.y, w2c, a2.y);
            a2.z = fmaf(sv.z, w2c, a2.z); a2.w = fmaf(sv.w, w2c, a2.w);
        }
        #pragma unroll
        for (int d = 0; d < 3; d++) {
            float4 a = (d == 0) ? a0 : (d == 1) ? a1 : a2;
            __half2 lo = __floats2half2_rn(fmaf(0.2f, tanhf(a.x), 1.0f),
                                           fmaf(0.2f, tanhf(a.y), 1.0f));
            __half2 hi = __floats2half2_rn(fmaf(0.2f, tanhf(a.z), 1.0f),
                                           fmaf(0.2f, tanhf(a.w), 1.0f));
            *reinterpret_cast<__half2*>(&s_t[r][d][wq])     = lo;
            *reinterpret_cast<__half2*>(&s_t[r][d][wq + 2]) = hi;
        }
    }
    __syncthreads();

    // --- hoist this lane's multipliers: 4 rows x 3 dirs x 4 half2 regs ---
    const int w0 = tx * 8;
    __half2 st[4][3][4];
    #pragma unroll
    for (int r = 0; r < 4; r++)
        #pragma unroll
        for (int dir = 0; dir < 3; dir++)
            #pragma unroll
            for (int j = 0; j < 4; j++)
                st[r][dir][j] =
                    *reinterpret_cast<const __half2*>(&s_t[r][dir][w0 + 2 * j]);

    const int hm = (h0 - 1) & (H - 1);
    const int hp = (h0 + 4) & (H - 1);
    const size_t base = (size_t)b * C * HW + (size_t)ty * HW + w0;
    const float* pm = x + base + (size_t)hm * W;
    const float* p0 = x + base + (size_t)h0 * W;
    const float* pp = x + base + (size_t)hp * W;
    float*       o0 = out + base + (size_t)h0 * W;
    const size_t cstep = (size_t)8 * HW;

    const unsigned FULL = 0xffffffffu;
    const int laneL = (tx + 31) & 31;
    const int laneR = (tx + 1) & 31;
    const __half2 zero2 = __float2half2_rn(0.0f);
    const __half2 cap2  = __float2half2_rn(GAIN_CAP);

    float invh, invv, invd;
    __half2 gh2, gv2, gd2;

    // one output row: centers (cA,cB), vertical sums (sA,sB), mults st[r]
    auto do_row = [&](float4 cA_, float4 cB_, float4 sA_, float4 sB_,
                      __half2 (&stR)[3][4], float* op) {
        float ce[10], se[10];
        ce[1] = cA_.x; ce[2] = cA_.y; ce[3] = cA_.z; ce[4] = cA_.w;
        ce[5] = cB_.x; ce[6] = cB_.y; ce[7] = cB_.z; ce[8] = cB_.w;
        se[1] = sA_.x; se[2] = sA_.y; se[3] = sA_.z; se[4] = sA_.w;
        se[5] = sB_.x; se[6] = sB_.y; se[7] = sB_.z; se[8] = sB_.w;
        ce[0] = __shfl_sync(FULL, ce[8], laneL);
        ce[9] = __shfl_sync(FULL, ce[1], laneR);
        se[0] = __shfl_sync(FULL, se[8], laneL);
        se[9] = __shfl_sync(FULL, se[1], laneR);

        float r8[8];
        #pragma unroll
        for (int j = 0; j < 4; j++) {
            __half2 gH = __hmin2(__hmax2(__hmul2(gh2, stR[0][j]), zero2), cap2);
            __half2 gV = __hmin2(__hmax2(__hmul2(gv2, stR[1][j]), zero2), cap2);
            __half2 gD = __hmin2(__hmax2(__hmul2(gd2, stR[2][j]), zero2), cap2);
            float2 ghf = __half22float2(gH);
            float2 gvf = __half22float2(gV);
            float2 gdf = __half22float2(gD);
            #pragma unroll
            for (int k = 0; k < 2; k++) {
                const int i = 2 * j + k;
                float cv = ce[i + 1];
                float fh = (ce[i] + ce[i + 2] - 2.0f * cv) * invh;
                float fv = (se[i + 1]          - 2.0f * cv) * invv;
                float fd = (se[i] + se[i + 2]  - 4.0f * cv) * invd;
                float gh = k ? ghf.y : ghf.x;
                float gv = k ? gvf.y : gvf.x;
                float gd = k ? gdf.y : gdf.x;
                r8[i] = fmaf(gh, fh, fmaf(gv, fv, fmaf(gd, fd, cv)));
            }
        }
        __stcs(reinterpret_cast<float4*>(op),
               make_float4(r8[0], r8[1], r8[2], r8[3]));
        __stcs(reinterpret_cast<float4*>(op + 4),
               make_float4(r8[4], r8[5], r8[6], r8[7]));
    };

    for (int c = ty; c < C; c += 8) {
        // front-batch all 12 row-vector loads (rows m, a, b, c, d, p)
        float4 mA = *reinterpret_cast<const float4*>(pm);
        float4 mB = *reinterpret_cast<const float4*>(pm + 4);
        float4 aA = *reinterpret_cast<const float4*>(p0);
        float4 aB = *reinterpret_cast<const float4*>(p0 + 4);
        float4 bA = *reinterpret_cast<const float4*>(p0 + W);
        float4 bB = *reinterpret_cast<const float4*>(p0 + W + 4);
        float4 cA = *reinterpret_cast<const float4*>(p0 + 2 * W);
        float4 cB = *reinterpret_cast<const float4*>(p0 + 2 * W + 4);
        float4 dA = *reinterpret_cast<const float4*>(p0 + 3 * W);
        float4 dB = *reinterpret_cast<const float4*>(p0 + 3 * W + 4);
        float4 pA = *reinterpret_cast<const float4*>(pp);
        float4 pB = *reinterpret_cast<const float4*>(pp + 4);

        invh = s_invh[c]; invv = s_invv[c]; invd = s_invd[c];
        gh2 = __float2half2_rn(s_gh[c]);
        gv2 = __float2half2_rn(s_gv[c]);
        gd2 = __float2half2_rn(s_gd[c]);

        // row h0: vsum = m + b
        do_row(aA, aB, add4(mA, bA), add4(mB, bB), st[0], o0);
        // row h1: vsum = a + c
        do_row(bA, bB, add4(aA, cA), add4(aB, cB), st[1], o0 + W);
        // row h2: vsum = b + d
        do_row(cA, cB, add4(bA, dA), add4(bB, dB), st[2], o0 + 2 * W);
        // row h3: vsum = c + p
        do_row(dA, dB, add4(cA, pA), add4(cB, pB), st[3], o0 + 3 * W);

        pm += cstep; p0 += cstep; pp += cstep; o0 += cstep;
    }
}

extern "C" void kernel_launch(void* const* d_in, const int* in_sizes, int n_in,
                              void* d_out, int out_size)
{
    const float* x            = (const float*)d_in[0];
    const float* steer        = (const float*)d_in[1];
    const float* modulation   = (const float*)d_in[2];
    const float* r_center     = (const float*)d_in[3];
    const float* r_horizontal = (const float*)d_in[4];
    const float* r_vertical   = (const float*)d_in[5];
    const float* r_diag       = (const float*)d_in[6];
    const float* gain_h       = (const float*)d_in[7];
    const float* gain_v       = (const float*)d_in[8];
    const float* gain_d       = (const float*)d_in[9];
    const float* steer_w      = (const float*)d_in[10];
    const float* mod_w        = (const float*)d_in[11];
    float* out = (float*)d_out;

    dim3 block(32, 8, 1);       // one warp per full W row-quad, 8 channel lanes
    dim3 grid(H / 4, B, 1);     // one block per (4-row group, b)
    pwdm_kernel<<<grid, block>>>(x, steer, modulation,
                                 r_center, r_horizontal, r_vertical, r_diag,
                                 gain_h, gain_v, gain_d,
                                 steer_w, mod_w, out);
}